// round 4
// baseline (speedup 1.0000x reference)
#include <cuda_runtime.h>

// SkelConv v4: FFMA2-dense with parity-shifted accumulators.
// x: (32,103,8192) f32, w: (206,103,15) masked block-tridiagonal, out: (32,206,8192).
//
// CTA = (time tile 256, pseudo-joint, batch), 128 threads = 8 co-slots x 16 time-segs.
// Thread computes 16 consecutive outputs for one out-channel.
// x tile staged in SMEM (XOR-swizzled 16B chunks, conflict-free strided windows).
// Odd taps -> accA pairs {2p,2p+1}; even taps -> accB pairs {2p+1,2p+2}; both use
// ONLY even-aligned x pairs straight from LDS.128 (no pack MOVs in hot loop).

#define C_IN   103
#define C_OUT  206
#define KK     15
#define TLEN   8192
#define NB     32
#define TPB    128
#define TT     256
#define TH     16
#define ROW_CHUNKS 70      // 280 floats per xs row (16B units)
#define ROW_STRIDE 80      // padded physical chunks per row

typedef unsigned long long u64;

__device__ __forceinline__ void unpack2(u64 v, float& lo, float& hi) {
    asm("mov.b64 {%0, %1}, %2;" : "=f"(lo), "=f"(hi) : "l"(v));
}
__device__ __forceinline__ void ffma2(u64& d, u64 a, u64 b) {
    asm("fma.rn.f32x2 %0, %1, %2, %0;" : "+l"(d) : "l"(a), "l"(b));
}
__device__ __forceinline__ int swz(int m) { return m ^ ((m >> 3) & 7); }

// y = 0..25: 0,1 = root halves (7 out ch each), y>=2 -> joint j=y-1 (8 out ch)
__device__ __forceinline__ void jp(int y, int& i0, int& iw, int& o0, int& ow) {
    if (y == 0)      { i0 = 0;  iw = 11; o0 = 0; ow = 7; }
    else if (y == 1) { i0 = 0;  iw = 11; o0 = 7; ow = 7; }
    else {
        const int j = y - 1;
        o0 = 14 + (j - 1) * 8; ow = 8;
        if (j == 1)       { i0 = 0;              iw = 15; }
        else if (j == 24) { i0 = 95;             iw = 8;  }
        else              { i0 = 7 + (j - 2) * 4; iw = 12; }
    }
}

__global__ void __launch_bounds__(TPB)
skel_conv4_kernel(const float* __restrict__ x,
                  const float* __restrict__ w,
                  const float* __restrict__ bias,
                  const float* __restrict__ mask,
                  float* __restrict__ out)
{
    int i0, iw, o0, ow;
    jp(blockIdx.y, i0, iw, o0, ow);

    const int b     = blockIdx.z;
    const int tid   = threadIdx.x;
    const int tile0 = blockIdx.x * TT;

    // xs[ci][chunk]: x[i0+ci][tile0-8 + 4*chunk ...], swizzled chunk placement.
    __shared__ float4 xs[15 * ROW_STRIDE];                 // 19200 B
    // wsh4[ci][co][q] = {w(2q),w(2q), w(2q+1),w(2q+1)} masked, q=0..7 (k=15 -> 0)
    __shared__ float4 wsh4[15][8][8];                      // 15360 B

    // ---- stage x ----
    {
        const float* xb = x + (size_t)b * C_IN * TLEN;
        const bool interior = (blockIdx.x > 0) && (blockIdx.x + 1 < gridDim.x);
        const int total = iw * ROW_CHUNKS;
        if (interior) {
            for (int idx = tid; idx < total; idx += TPB) {
                const int ci = idx / ROW_CHUNKS;
                const int m  = idx - ci * ROW_CHUNKS;
                const float4* src = reinterpret_cast<const float4*>(
                    xb + (size_t)(i0 + ci) * TLEN + tile0 - 8);
                xs[ci * ROW_STRIDE + swz(m)] = src[m];
            }
        } else {
            for (int idx = tid; idx < total; idx += TPB) {
                const int ci = idx / ROW_CHUNKS;
                const int m  = idx - ci * ROW_CHUNKS;
                const float* xrow = xb + (size_t)(i0 + ci) * TLEN;
                float4 v;
                const int g0 = tile0 - 8 + m * 4;
                v.x = (g0 + 0 >= 0 && g0 + 0 < TLEN) ? xrow[g0 + 0] : 0.0f;
                v.y = (g0 + 1 >= 0 && g0 + 1 < TLEN) ? xrow[g0 + 1] : 0.0f;
                v.z = (g0 + 2 >= 0 && g0 + 2 < TLEN) ? xrow[g0 + 2] : 0.0f;
                v.w = (g0 + 3 >= 0 && g0 + 3 < TLEN) ? xrow[g0 + 3] : 0.0f;
                xs[ci * ROW_STRIDE + swz(m)] = v;
            }
        }
    }
    // ---- stage masked duplicated weights ----
    {
        const int total = iw * 8 * 8;
        for (int idx = tid; idx < total; idx += TPB) {
            const int q  = idx & 7;
            const int co = (idx >> 3) & 7;
            const int ci = idx >> 6;
            float a = 0.0f, c = 0.0f;
            if (co < ow) {
                const int gi = ((o0 + co) * C_IN + (i0 + ci)) * KK;
                a = w[gi + 2 * q] * mask[gi + 2 * q];
                if (2 * q + 1 < KK) c = w[gi + 2 * q + 1] * mask[gi + 2 * q + 1];
            }
            wsh4[ci][co][q] = make_float4(a, a, c, c);
        }
    }
    __syncthreads();

    const int co   = tid >> 4;
    const int tseg = tid & 15;
    const int T0   = tile0 + tseg * TH;

    u64 accA[8];     // odd taps, out pairs {T0+2p, T0+2p+1}
    u64 accB[9];     // even taps, out pairs {T0+2p-1, T0+2p} (index j = p+1... j covers p-1..7)
#pragma unroll
    for (int p = 0; p < 8; p++) accA[p] = 0ull;
#pragma unroll
    for (int j = 0; j < 9; j++) accB[j] = 0ull;

    for (int ci = 0; ci < iw; ci++) {
        // xe[i] = {x[T0-8+2i], x[T0-8+2i+1]}, i = 0..15 : straight from LDS.128.
        u64 xe[16];
        const float4* xrow = &xs[ci * ROW_STRIDE];
        const int mbase = tseg * 4;
#pragma unroll
        for (int q = 0; q < 8; q++) {
            const ulonglong2 v = *reinterpret_cast<const ulonglong2*>(
                &xrow[swz(mbase + q)]);
            xe[2 * q]     = v.x;
            xe[2 * q + 1] = v.y;
        }

        const ulonglong2* wq = reinterpret_cast<const ulonglong2*>(&wsh4[ci][co][0]);
#pragma unroll
        for (int q = 0; q < 8; q++) {
            const ulonglong2 wv = wq[q];   // .x = dup w(2q), .y = dup w(2q+1)
            // even tap k=2q: accB[j] (logical p=j-1) uses xe[q+j]
#pragma unroll
            for (int j = 0; j < 9; j++) ffma2(accB[j], wv.x, xe[q + j]);
            // odd tap k=2q+1 (k<15): accA[p] uses xe[q+1+p]
            if (q < 7) {
#pragma unroll
                for (int p = 0; p < 8; p++) ffma2(accA[p], wv.y, xe[q + 1 + p]);
            }
        }
    }

    // ---- combine parities + bias + store ----
    if (co < ow) {
        const float bv = bias[o0 + co];
        float* ob = out + ((size_t)b * C_OUT + (o0 + co)) * TLEN + T0;
        float aLo[8], aHi[8], bLo[9], bHi[9];
#pragma unroll
        for (int p = 0; p < 8; p++) unpack2(accA[p], aLo[p], aHi[p]);
#pragma unroll
        for (int j = 0; j < 9; j++) unpack2(accB[j], bLo[j], bHi[j]);
#pragma unroll
        for (int p = 0; p < 8; p += 2) {
            float4 r;
            r.x = aLo[p]     + bHi[p]     + bv;   // out[T0+2p]
            r.y = aHi[p]     + bLo[p + 1] + bv;   // out[T0+2p+1]
            r.z = aLo[p + 1] + bHi[p + 1] + bv;   // out[T0+2p+2]
            r.w = aHi[p + 1] + bLo[p + 2] + bv;   // out[T0+2p+3]
            *reinterpret_cast<float4*>(ob + 2 * p) = r;
        }
    }
}

extern "C" void kernel_launch(void* const* d_in, const int* in_sizes, int n_in,
                              void* d_out, int out_size)
{
    (void)in_sizes; (void)n_in; (void)out_size;
    const float* x    = (const float*)d_in[0];
    const float* w    = (const float*)d_in[1];
    const float* bias = (const float*)d_in[2];
    const float* mask = (const float*)d_in[3];
    float* out = (float*)d_out;

    dim3 grid(TLEN / TT, 26, NB);
    skel_conv4_kernel<<<grid, TPB>>>(x, w, bias, mask, out);
}

// round 5
// speedup vs baseline: 1.0299x; 1.0299x over previous
#include <cuda_runtime.h>

// SkelConv v5: R2 structure (register x-window via LDG, weights in SMEM)
// with U=8 time-steps/thread -> 4 independent FFMA2 chains per out-channel,
// halved LDS- and LDG-per-FMA vs R2.
//
// Thread (co, tseg): co = tid>>4 (8 out-ch slots), tseg = tid&15.
// Each thread computes 8 consecutive outputs T0..T0+7 for its out-channel.

#define C_IN   103
#define C_OUT  206
#define KK     15
#define TLEN   8192
#define NB     32
#define U      8
#define TPB    128
#define TT     128          // 16 tsegs * 8
#define OW     8

typedef unsigned long long u64;

__device__ __forceinline__ u64 pack2(float lo, float hi) {
    u64 r;
    asm("mov.b64 %0, {%1, %2};" : "=l"(r) : "f"(lo), "f"(hi));
    return r;
}
__device__ __forceinline__ void unpack2(u64 v, float& lo, float& hi) {
    asm("mov.b64 {%0, %1}, %2;" : "=f"(lo), "=f"(hi) : "l"(v));
}
__device__ __forceinline__ void ffma2(u64& d, u64 a, u64 b) {
    asm("fma.rn.f32x2 %0, %1, %2, %0;" : "+l"(d) : "l"(a), "l"(b));
}
// {hi(a), lo(b)}
__device__ __forceinline__ u64 mkodd(u64 a, u64 b) {
    float alo, ahi, blo, bhi;
    unpack2(a, alo, ahi);
    unpack2(b, blo, bhi);
    return pack2(ahi, blo);
}

// y = 0..25: 0,1 = root halves (7 out ch each), y>=2 -> joint j=y-1 (8 out ch)
__device__ __forceinline__ void jp(int y, int& i0, int& iw, int& o0, int& ow) {
    if (y == 0)      { i0 = 0;  iw = 11; o0 = 0; ow = 7; }
    else if (y == 1) { i0 = 0;  iw = 11; o0 = 7; ow = 7; }
    else {
        const int j = y - 1;
        o0 = 14 + (j - 1) * 8; ow = 8;
        if (j == 1)       { i0 = 0;              iw = 15; }
        else if (j == 24) { i0 = 95;             iw = 8;  }
        else              { i0 = 7 + (j - 2) * 4; iw = 12; }
    }
}

__global__ void __launch_bounds__(TPB)
skel_conv5_kernel(const float* __restrict__ x,
                  const float* __restrict__ w,
                  const float* __restrict__ bias,
                  const float* __restrict__ mask,
                  float* __restrict__ out)
{
    int i0, iw, o0, ow;
    jp(blockIdx.y, i0, iw, o0, ow);

    const int b    = blockIdx.z;
    const int tid  = threadIdx.x;
    const int co   = tid >> 4;
    const int tseg = tid & 15;
    const int T0   = blockIdx.x * TT + tseg * U;

    // Masked weights, duplicated {w,w}, K padded to 16 pairs per (co,ci).
    __shared__ float2 wsh[OW][15][16];
    {
        const int total = OW * iw * 16;
        for (int idx = tid; idx < total; idx += TPB) {
            const int k  = idx & 15;
            const int r  = idx >> 4;
            const int ci = r % iw;
            const int c  = r / iw;
            float v = 0.0f;
            if (k < KK && c < ow) {
                const int gi = ((o0 + c) * C_IN + (i0 + ci)) * KK + k;
                v = w[gi] * mask[gi];
            }
            wsh[c][ci][k] = make_float2(v, v);
        }
    }
    __syncthreads();

    // acc[p] pair = outputs {T0+2p, T0+2p+1}, p = 0..3.  (4 chains)
    u64 acc[4];
#pragma unroll
    for (int p = 0; p < 4; p++) acc[p] = 0ull;

    const bool interior = (T0 - 8 >= 0) && (T0 + 16 <= TLEN);
    const float* xb = x + (size_t)b * C_IN * TLEN;

    for (int ci = 0; ci < iw; ci++) {
        const float* xrow = xb + (size_t)(i0 + ci) * TLEN;

        // Window x[T0-8 .. T0+15]: xe[i] = {x[T0-8+2i], x[T0-8+2i+1]}, i=0..11.
        u64 xe[12];
        if (interior) {
            const ulonglong2* xq =
                reinterpret_cast<const ulonglong2*>(xrow + T0 - 8);
#pragma unroll
            for (int q = 0; q < 6; q++) {
                const ulonglong2 v = xq[q];
                xe[2 * q]     = v.x;
                xe[2 * q + 1] = v.y;
            }
        } else {
#pragma unroll
            for (int i = 0; i < 12; i++) {
                const int t = T0 - 8 + 2 * i;
                const float lo = (t >= 0 && t < TLEN) ? xrow[t] : 0.0f;
                const float hi = (t + 1 >= 0 && t + 1 < TLEN) ? xrow[t + 1] : 0.0f;
                xe[i] = pack2(lo, hi);
            }
        }

        // Odd pairs xo[i] = {x[T0-7+2i], x[T0-6+2i]}, i = 0..10.
        u64 xo[11];
#pragma unroll
        for (int i = 0; i < 11; i++) xo[i] = mkodd(xe[i], xe[i + 1]);

        const ulonglong2* wq =
            reinterpret_cast<const ulonglong2*>(&wsh[co][ci][0]);
#pragma unroll
        for (int q = 0; q < 8; q++) {
            const ulonglong2 wv = wq[q];   // .x = dup w(2q), .y = dup w(2q+1)
            // even tap k = 2q: x offset m = 2p+k+1 odd -> xo[p+q]
#pragma unroll
            for (int p = 0; p < 4; p++) ffma2(acc[p], wv.x, xo[p + q]);
            // odd tap k = 2q+1 (k < 15): m even -> xe[p+q+1]
            if (q < 7) {
#pragma unroll
                for (int p = 0; p < 4; p++) ffma2(acc[p], wv.y, xe[p + q + 1]);
            }
        }
    }

    if (co < ow) {
        const float bv = bias[o0 + co];
        float* ob = out + ((size_t)b * C_OUT + (o0 + co)) * TLEN + T0;
        float lo0, hi0, lo1, hi1;
        unpack2(acc[0], lo0, hi0);
        unpack2(acc[1], lo1, hi1);
        float4 r0 = make_float4(lo0 + bv, hi0 + bv, lo1 + bv, hi1 + bv);
        unpack2(acc[2], lo0, hi0);
        unpack2(acc[3], lo1, hi1);
        float4 r1 = make_float4(lo0 + bv, hi0 + bv, lo1 + bv, hi1 + bv);
        *reinterpret_cast<float4*>(ob)     = r0;
        *reinterpret_cast<float4*>(ob + 4) = r1;
    }
}

extern "C" void kernel_launch(void* const* d_in, const int* in_sizes, int n_in,
                              void* d_out, int out_size)
{
    (void)in_sizes; (void)n_in; (void)out_size;
    const float* x    = (const float*)d_in[0];
    const float* w    = (const float*)d_in[1];
    const float* bias = (const float*)d_in[2];
    const float* mask = (const float*)d_in[3];
    float* out = (float*)d_out;

    dim3 grid(TLEN / TT, 26, NB);
    skel_conv5_kernel<<<grid, TPB>>>(x, w, bias, mask, out);
}

// round 6
// speedup vs baseline: 1.4630x; 1.4206x over previous
#include <cuda_runtime.h>

// SkelConv v6: FFMA2 + parity-shifted accumulators + co-amortized register window.
// Thread = (co-group of 4 channels, 8 time steps). x window (24 floats) loaded
// once per ci via 6 aligned LDG.128 and reused for 4 out-channels -> 272 FFMA2
// per ci against 6 LDG + 32 broadcast LDS. No pack MOVs in the hot loop.

#define C_IN   103
#define C_OUT  206
#define KK     15
#define TLEN   8192
#define NB     32
#define TPB    128
#define U      8
#define TT     512          // 64 tsegs * 8
#define CG     4

typedef unsigned long long u64;

__device__ __forceinline__ u64 pack2(float lo, float hi) {
    u64 r;
    asm("mov.b64 %0, {%1, %2};" : "=l"(r) : "f"(lo), "f"(hi));
    return r;
}
__device__ __forceinline__ void unpack2(u64 v, float& lo, float& hi) {
    asm("mov.b64 {%0, %1}, %2;" : "=f"(lo), "=f"(hi) : "l"(v));
}
__device__ __forceinline__ void ffma2(u64& d, u64 a, u64 b) {
    asm("fma.rn.f32x2 %0, %1, %2, %0;" : "+l"(d) : "l"(a), "l"(b));
}

// y = 0..25: 0,1 = root halves (7 out ch each), y>=2 -> joint j=y-1 (8 out ch)
__device__ __forceinline__ void jp(int y, int& i0, int& iw, int& o0, int& ow) {
    if (y == 0)      { i0 = 0;  iw = 11; o0 = 0; ow = 7; }
    else if (y == 1) { i0 = 0;  iw = 11; o0 = 7; ow = 7; }
    else {
        const int j = y - 1;
        o0 = 14 + (j - 1) * 8; ow = 8;
        if (j == 1)       { i0 = 0;              iw = 15; }
        else if (j == 24) { i0 = 95;             iw = 8;  }
        else              { i0 = 7 + (j - 2) * 4; iw = 12; }
    }
}

__global__ void __launch_bounds__(TPB, 3)
skel_conv6_kernel(const float* __restrict__ x,
                  const float* __restrict__ w,
                  const float* __restrict__ bias,
                  const float* __restrict__ mask,
                  float* __restrict__ out)
{
    int i0, iw, o0, ow;
    jp(blockIdx.y, i0, iw, o0, ow);

    const int b   = blockIdx.z;
    const int tid = threadIdx.x;

    // wsh[ci][co][q] = {w(2q),w(2q), w(2q+1),w(2q+1)} masked (k=15 slot -> 0).
    __shared__ float4 wsh[15][8][8];
    {
        const int total = iw * 64;
        for (int idx = tid; idx < total; idx += TPB) {
            const int q  = idx & 7;
            const int co = (idx >> 3) & 7;
            const int ci = idx >> 6;
            float a = 0.0f, c = 0.0f;
            if (co < ow) {
                const int gi = ((o0 + co) * C_IN + (i0 + ci)) * KK;
                a = w[gi + 2 * q] * mask[gi + 2 * q];
                if (2 * q + 1 < KK) c = w[gi + 2 * q + 1] * mask[gi + 2 * q + 1];
            }
            wsh[ci][co][q] = make_float4(a, a, c, c);
        }
    }
    __syncthreads();

    const int g      = tid >> 6;          // co-group 0..1 (warps 0-1 / 2-3)
    const int ts     = tid & 63;
    const int cobase = g * CG;
    const int T0     = blockIdx.x * TT + ts * U;

    // accA[c][p]: odd taps, outputs {T0+2p, T0+2p+1}
    // accB[c][j]: even taps, outputs {T0+2j-1, T0+2j} (lo of j=0, hi of j=4 unused)
    u64 accA[CG][4], accB[CG][5];
#pragma unroll
    for (int c = 0; c < CG; c++) {
#pragma unroll
        for (int p = 0; p < 4; p++) accA[c][p] = 0ull;
#pragma unroll
        for (int j = 0; j < 5; j++) accB[c][j] = 0ull;
    }

    const bool interior = (T0 >= 8) && (T0 + 16 <= TLEN);
    const float* xb = x + (size_t)b * C_IN * TLEN;

    for (int ci = 0; ci < iw; ci++) {
        const float* xrow = xb + (size_t)(i0 + ci) * TLEN;

        // xe[i] = {x[T0-8+2i], x[T0-8+2i+1]}, i = 0..11 (window T0-8 .. T0+15)
        u64 xe[12];
        if (interior) {
            const ulonglong2* xq =
                reinterpret_cast<const ulonglong2*>(xrow + T0 - 8);
#pragma unroll
            for (int q = 0; q < 6; q++) {
                const ulonglong2 v = xq[q];
                xe[2 * q]     = v.x;
                xe[2 * q + 1] = v.y;
            }
        } else {
#pragma unroll
            for (int i = 0; i < 12; i++) {
                const int t = T0 - 8 + 2 * i;
                const float lo = (t >= 0 && t < TLEN) ? xrow[t] : 0.0f;
                const float hi = (t + 1 >= 0 && t + 1 < TLEN) ? xrow[t + 1] : 0.0f;
                xe[i] = pack2(lo, hi);
            }
        }

#pragma unroll
        for (int c = 0; c < CG; c++) {
            const ulonglong2* wq =
                reinterpret_cast<const ulonglong2*>(&wsh[ci][cobase + c][0]);
#pragma unroll
            for (int q = 0; q < 8; q++) {
                const ulonglong2 wv = wq[q];  // .x = dup w(2q), .y = dup w(2q+1)
                // even tap k=2q -> accB[j] uses xe[q+j]
#pragma unroll
                for (int jj = 0; jj < 5; jj++) ffma2(accB[c][jj], wv.x, xe[q + jj]);
                // odd tap k=2q+1 (k<15) -> accA[p] uses xe[q+1+p]
                if (q < 7) {
#pragma unroll
                    for (int p = 0; p < 4; p++) ffma2(accA[c][p], wv.y, xe[q + 1 + p]);
                }
            }
        }
    }

    // Combine parities + bias + store (8 outputs per co).
#pragma unroll
    for (int c = 0; c < CG; c++) {
        const int co = cobase + c;
        if (co < ow) {
            const float bv = bias[o0 + co];
            float* ob = out + ((size_t)b * C_OUT + (o0 + co)) * TLEN + T0;
            float aLo[4], aHi[4], bLo[5], bHi[5];
#pragma unroll
            for (int p = 0; p < 4; p++) unpack2(accA[c][p], aLo[p], aHi[p]);
#pragma unroll
            for (int j = 0; j < 5; j++) unpack2(accB[c][j], bLo[j], bHi[j]);
            float4 r0, r1;
            r0.x = aLo[0] + bHi[0] + bv;
            r0.y = aHi[0] + bLo[1] + bv;
            r0.z = aLo[1] + bHi[1] + bv;
            r0.w = aHi[1] + bLo[2] + bv;
            r1.x = aLo[2] + bHi[2] + bv;
            r1.y = aHi[2] + bLo[3] + bv;
            r1.z = aLo[3] + bHi[3] + bv;
            r1.w = aHi[3] + bLo[4] + bv;
            *reinterpret_cast<float4*>(ob)     = r0;
            *reinterpret_cast<float4*>(ob + 4) = r1;
        }
    }
}

extern "C" void kernel_launch(void* const* d_in, const int* in_sizes, int n_in,
                              void* d_out, int out_size)
{
    (void)in_sizes; (void)n_in; (void)out_size;
    const float* x    = (const float*)d_in[0];
    const float* w    = (const float*)d_in[1];
    const float* bias = (const float*)d_in[2];
    const float* mask = (const float*)d_in[3];
    float* out = (float*)d_out;

    dim3 grid(TLEN / TT, 26, NB);
    skel_conv6_kernel<<<grid, TPB>>>(x, w, bias, mask, out);
}

// round 7
// speedup vs baseline: 1.5557x; 1.0634x over previous
#include <cuda_runtime.h>

// SkelConv v7: v6 + software-pipelined (double-buffered) x window loads.
// Thread = (co-group of 4, 8 time steps). Window for ci+1 is issued before the
// FFMA2 block of ci, hiding L2 latency under ~540 cycles of FMA per warp.

#define C_IN   103
#define C_OUT  206
#define KK     15
#define TLEN   8192
#define NB     32
#define TPB    128
#define U      8
#define TT     512          // 64 tsegs * 8
#define CG     4

typedef unsigned long long u64;

__device__ __forceinline__ u64 pack2(float lo, float hi) {
    u64 r;
    asm("mov.b64 %0, {%1, %2};" : "=l"(r) : "f"(lo), "f"(hi));
    return r;
}
__device__ __forceinline__ void unpack2(u64 v, float& lo, float& hi) {
    asm("mov.b64 {%0, %1}, %2;" : "=f"(lo), "=f"(hi) : "l"(v));
}
__device__ __forceinline__ void ffma2(u64& d, u64 a, u64 b) {
    asm("fma.rn.f32x2 %0, %1, %2, %0;" : "+l"(d) : "l"(a), "l"(b));
}

// y = 0..25: 0,1 = root halves (7 out ch each), y>=2 -> joint j=y-1 (8 out ch)
__device__ __forceinline__ void jp(int y, int& i0, int& iw, int& o0, int& ow) {
    if (y == 0)      { i0 = 0;  iw = 11; o0 = 0; ow = 7; }
    else if (y == 1) { i0 = 0;  iw = 11; o0 = 7; ow = 7; }
    else {
        const int j = y - 1;
        o0 = 14 + (j - 1) * 8; ow = 8;
        if (j == 1)       { i0 = 0;              iw = 15; }
        else if (j == 24) { i0 = 95;             iw = 8;  }
        else              { i0 = 7 + (j - 2) * 4; iw = 12; }
    }
}

__device__ __forceinline__ void load_window(u64 (&xe)[12], const float* __restrict__ xrow,
                                            int T0, bool interior) {
    if (interior) {
        const ulonglong2* xq = reinterpret_cast<const ulonglong2*>(xrow + T0 - 8);
#pragma unroll
        for (int q = 0; q < 6; q++) {
            const ulonglong2 v = xq[q];
            xe[2 * q]     = v.x;
            xe[2 * q + 1] = v.y;
        }
    } else {
#pragma unroll
        for (int i = 0; i < 12; i++) {
            const int t = T0 - 8 + 2 * i;
            const float lo = (t >= 0 && t < TLEN) ? xrow[t] : 0.0f;
            const float hi = (t + 1 >= 0 && t + 1 < TLEN) ? xrow[t + 1] : 0.0f;
            xe[i] = pack2(lo, hi);
        }
    }
}

__global__ void __launch_bounds__(TPB, 3)
skel_conv7_kernel(const float* __restrict__ x,
                  const float* __restrict__ w,
                  const float* __restrict__ bias,
                  const float* __restrict__ mask,
                  float* __restrict__ out)
{
    int i0, iw, o0, ow;
    jp(blockIdx.y, i0, iw, o0, ow);

    const int b   = blockIdx.z;
    const int tid = threadIdx.x;

    // wsh[ci][co][q] = {w(2q),w(2q), w(2q+1),w(2q+1)} masked (k=15 slot -> 0).
    __shared__ float4 wsh[15][8][8];
    {
        const int total = iw * 64;
        for (int idx = tid; idx < total; idx += TPB) {
            const int q  = idx & 7;
            const int co = (idx >> 3) & 7;
            const int ci = idx >> 6;
            float a = 0.0f, c = 0.0f;
            if (co < ow) {
                const int gi = ((o0 + co) * C_IN + (i0 + ci)) * KK;
                a = w[gi + 2 * q] * mask[gi + 2 * q];
                if (2 * q + 1 < KK) c = w[gi + 2 * q + 1] * mask[gi + 2 * q + 1];
            }
            wsh[ci][co][q] = make_float4(a, a, c, c);
        }
    }
    __syncthreads();

    const int g      = tid >> 6;          // co-group 0..1
    const int ts     = tid & 63;
    const int cobase = g * CG;
    const int T0     = blockIdx.x * TT + ts * U;

    u64 accA[CG][4], accB[CG][5];
#pragma unroll
    for (int c = 0; c < CG; c++) {
#pragma unroll
        for (int p = 0; p < 4; p++) accA[c][p] = 0ull;
#pragma unroll
        for (int j = 0; j < 5; j++) accB[c][j] = 0ull;
    }

    const bool interior = (T0 >= 8) && (T0 + 16 <= TLEN);
    const float* xb = x + (size_t)b * C_IN * TLEN + T0;

#define COMPUTE(XE, CI)                                                        \
    {                                                                          \
        _Pragma("unroll")                                                      \
        for (int c = 0; c < CG; c++) {                                         \
            const ulonglong2* wq = reinterpret_cast<const ulonglong2*>(        \
                &wsh[CI][cobase + c][0]);                                      \
            _Pragma("unroll")                                                  \
            for (int q = 0; q < 8; q++) {                                      \
                const ulonglong2 wv = wq[q];                                   \
                _Pragma("unroll")                                              \
                for (int jj = 0; jj < 5; jj++)                                 \
                    ffma2(accB[c][jj], wv.x, (XE)[q + jj]);                    \
                if (q < 7) {                                                   \
                    _Pragma("unroll")                                          \
                    for (int p = 0; p < 4; p++)                                \
                        ffma2(accA[c][p], wv.y, (XE)[q + 1 + p]);              \
                }                                                              \
            }                                                                  \
        }                                                                      \
    }

    {
        u64 xeA[12], xeB[12];
        load_window(xeA, xb + (size_t)i0 * TLEN - T0 + (size_t)0, T0, interior);
        // NOTE: xrow for ci is xb - T0 + (i0+ci)*TLEN + ... simplify below.
        const float* base = x + (size_t)b * C_IN * TLEN;
        load_window(xeA, base + (size_t)(i0 + 0) * TLEN, T0, interior);

        int ci = 0;
        while (true) {
            if (ci + 1 < iw)
                load_window(xeB, base + (size_t)(i0 + ci + 1) * TLEN, T0, interior);
            COMPUTE(xeA, ci);
            ci++;
            if (ci >= iw) break;
            if (ci + 1 < iw)
                load_window(xeA, base + (size_t)(i0 + ci + 1) * TLEN, T0, interior);
            COMPUTE(xeB, ci);
            ci++;
            if (ci >= iw) break;
        }
    }
#undef COMPUTE

#pragma unroll
    for (int c = 0; c < CG; c++) {
        const int co = cobase + c;
        if (co < ow) {
            const float bv = bias[o0 + co];
            float* ob = out + ((size_t)b * C_OUT + (o0 + co)) * TLEN + T0;
            float aLo[4], aHi[4], bLo[5], bHi[5];
#pragma unroll
            for (int p = 0; p < 4; p++) unpack2(accA[c][p], aLo[p], aHi[p]);
#pragma unroll
            for (int j = 0; j < 5; j++) unpack2(accB[c][j], bLo[j], bHi[j]);
            float4 r0, r1;
            r0.x = aLo[0] + bHi[0] + bv;
            r0.y = aHi[0] + bLo[1] + bv;
            r0.z = aLo[1] + bHi[1] + bv;
            r0.w = aHi[1] + bLo[2] + bv;
            r1.x = aLo[2] + bHi[2] + bv;
            r1.y = aHi[2] + bLo[3] + bv;
            r1.z = aLo[3] + bHi[3] + bv;
            r1.w = aHi[3] + bLo[4] + bv;
            *reinterpret_cast<float4*>(ob)     = r0;
            *reinterpret_cast<float4*>(ob + 4) = r1;
        }
    }
}

extern "C" void kernel_launch(void* const* d_in, const int* in_sizes, int n_in,
                              void* d_out, int out_size)
{
    (void)in_sizes; (void)n_in; (void)out_size;
    const float* x    = (const float*)d_in[0];
    const float* w    = (const float*)d_in[1];
    const float* bias = (const float*)d_in[2];
    const float* mask = (const float*)d_in[3];
    float* out = (float*)d_out;

    dim3 grid(TLEN / TT, 26, NB);
    skel_conv7_kernel<<<grid, TPB>>>(x, w, bias, mask, out);
}